// round 12
// baseline (speedup 1.0000x reference)
#include <cuda_runtime.h>
#include <math.h>

#define LSEQ 4096
#define DD   192
#define BB   2
#define TOT  (BB*LSEQ*DD)
#define LOG2E 1.4426950408889634f

// ---------------- scratch ----------------
__device__ __align__(16) float2 g_BC[TOT];   // [b][l][n] -> (B, C)
__device__ __align__(16) float2 g_dd[TOT];   // [b][d][l] -> (delta, delta*u)
__device__ __align__(16) float  g_uT[TOT];   // [b][d][l]

// ---------------- helpers ----------------
__device__ __forceinline__ float ex2f(float x) {
    float y;
    asm("ex2.approx.ftz.f32 %0, %1;" : "=f"(y) : "f"(x));
    return y;
}
__device__ __forceinline__ float softplus_f(float x) {
    if (x > 20.0f) return x;
    return log1pf(expf(x));
}
__device__ __forceinline__ void cp16(float* smem_dst, const float* gmem_src) {
    unsigned s = (unsigned)__cvta_generic_to_shared(smem_dst);
    asm volatile("cp.async.cg.shared.global [%0], [%1], 16;\n" :: "r"(s), "l"(gmem_src));
}
__device__ __forceinline__ void cp_commit() { asm volatile("cp.async.commit_group;\n" ::: "memory"); }
__device__ __forceinline__ void cp_wait0()  { asm volatile("cp.async.wait_group 0;\n" ::: "memory"); }

// ---------------- K1a: fused tokenize + B&C projections ----------------
__global__ void projBC_kernel(const float* __restrict__ x,
                              const float* __restrict__ W_B, const float* __restrict__ b_B,
                              const float* __restrict__ W_C, const float* __restrict__ b_C) {
    __shared__ __align__(16) float As[16][128];
    __shared__ __align__(16) float Bs[16][64];
    __shared__ __align__(16) float Cs[16][64];

    int tid = threadIdx.x;
    int tx = tid & 15;
    int ty = tid >> 4;
    int m0 = blockIdx.x * 128;
    int jw0 = blockIdx.y * 64;

    float accB[8][4], accC[8][4];
#pragma unroll
    for (int i = 0; i < 8; i++)
#pragma unroll
        for (int j = 0; j < 4; j++) { accB[i][j] = 0.0f; accC[i][j] = 0.0f; }

    for (int kt = 0; kt < 12; kt++) {
        int k0 = kt * 16;
#pragma unroll
        for (int r = 0; r < 2; r++) {
            int idx  = tid + r * 256;
            int mrow = idx >> 2;
            int kq   = idx & 3;
            int m = m0 + mrow;
            int b = m >> 12;
            int l = m & 4095;
            int ih = l >> 6;
            int iw = l & 63;
            int c  = (k0 >> 2) + kq;
            const float* xb = x + (((b * 48 + c) * 128 + ih * 2) * 128 + iw * 2);
            float2 v01 = *(const float2*)xb;
            float2 v23 = *(const float2*)(xb + 128);
            As[kq * 4 + 0][mrow] = v01.x;
            As[kq * 4 + 1][mrow] = v01.y;
            As[kq * 4 + 2][mrow] = v23.x;
            As[kq * 4 + 3][mrow] = v23.y;
        }
        {
            int jrow = tid >> 2;
            int kq   = tid & 3;
            float4 vb = *(const float4*)&W_B[(jw0 + jrow) * 192 + k0 + kq * 4];
            float4 vc = *(const float4*)&W_C[(jw0 + jrow) * 192 + k0 + kq * 4];
            Bs[kq * 4 + 0][jrow] = vb.x; Bs[kq * 4 + 1][jrow] = vb.y;
            Bs[kq * 4 + 2][jrow] = vb.z; Bs[kq * 4 + 3][jrow] = vb.w;
            Cs[kq * 4 + 0][jrow] = vc.x; Cs[kq * 4 + 1][jrow] = vc.y;
            Cs[kq * 4 + 2][jrow] = vc.z; Cs[kq * 4 + 3][jrow] = vc.w;
        }
        __syncthreads();
#pragma unroll
        for (int kk = 0; kk < 16; kk++) {
            float4 a0 = *(const float4*)&As[kk][ty * 8];
            float4 a1 = *(const float4*)&As[kk][ty * 8 + 4];
            float4 bv = *(const float4*)&Bs[kk][tx * 4];
            float4 cv = *(const float4*)&Cs[kk][tx * 4];
            float a[8] = {a0.x, a0.y, a0.z, a0.w, a1.x, a1.y, a1.z, a1.w};
            float bb[4] = {bv.x, bv.y, bv.z, bv.w};
            float cc[4] = {cv.x, cv.y, cv.z, cv.w};
#pragma unroll
            for (int i = 0; i < 8; i++)
#pragma unroll
                for (int j = 0; j < 4; j++) {
                    accB[i][j] = fmaf(a[i], bb[j], accB[i][j]);
                    accC[i][j] = fmaf(a[i], cc[j], accC[i][j]);
                }
        }
        __syncthreads();
    }

    int ncol = jw0 + tx * 4;
    float4 bB4 = *(const float4*)&b_B[ncol];
    float4 bC4 = *(const float4*)&b_C[ncol];
#pragma unroll
    for (int i = 0; i < 8; i++) {
        int m = m0 + ty * 8 + i;
        float4 o01, o23;
        o01.x = accB[i][0] + bB4.x; o01.y = accC[i][0] + bC4.x;
        o01.z = accB[i][1] + bB4.y; o01.w = accC[i][1] + bC4.y;
        o23.x = accB[i][2] + bB4.z; o23.y = accC[i][2] + bC4.z;
        o23.z = accB[i][3] + bB4.w; o23.w = accC[i][3] + bC4.w;
        *(float4*)&g_BC[m * 192 + ncol]     = o01;
        *(float4*)&g_BC[m * 192 + ncol + 2] = o23;
    }
}

// ---------------- K1b: fused tokenize + dt projection ----------------
__global__ void projDT_kernel(const float* __restrict__ x,
                              const float* __restrict__ W_dt, const float* __restrict__ b_dt) {
    __shared__ __align__(16) float As[16][128];
    __shared__ __align__(16) float Bs[16][64];

    int tid = threadIdx.x;
    int tx = tid & 15;
    int ty = tid >> 4;
    int m0 = blockIdx.x * 128;
    int jw0 = blockIdx.y * 64;

    float acc[8][4];
#pragma unroll
    for (int i = 0; i < 8; i++)
#pragma unroll
        for (int j = 0; j < 4; j++) acc[i][j] = 0.0f;

    for (int kt = 0; kt < 12; kt++) {
        int k0 = kt * 16;
#pragma unroll
        for (int r = 0; r < 2; r++) {
            int idx  = tid + r * 256;
            int mrow = idx >> 2;
            int kq   = idx & 3;
            int m = m0 + mrow;
            int b = m >> 12;
            int l = m & 4095;
            int ih = l >> 6;
            int iw = l & 63;
            int c  = (k0 >> 2) + kq;
            const float* xb = x + (((b * 48 + c) * 128 + ih * 2) * 128 + iw * 2);
            float2 v01 = *(const float2*)xb;
            float2 v23 = *(const float2*)(xb + 128);
            As[kq * 4 + 0][mrow] = v01.x;
            As[kq * 4 + 1][mrow] = v01.y;
            As[kq * 4 + 2][mrow] = v23.x;
            As[kq * 4 + 3][mrow] = v23.y;
        }
        {
            int jrow = tid >> 2;
            int kq   = tid & 3;
            float4 v = *(const float4*)&W_dt[(jw0 + jrow) * 192 + k0 + kq * 4];
            Bs[kq * 4 + 0][jrow] = v.x; Bs[kq * 4 + 1][jrow] = v.y;
            Bs[kq * 4 + 2][jrow] = v.z; Bs[kq * 4 + 3][jrow] = v.w;
        }
        __syncthreads();
#pragma unroll
        for (int kk = 0; kk < 16; kk++) {
            float4 a0 = *(const float4*)&As[kk][ty * 8];
            float4 a1 = *(const float4*)&As[kk][ty * 8 + 4];
            float4 bv = *(const float4*)&Bs[kk][tx * 4];
            float a[8] = {a0.x, a0.y, a0.z, a0.w, a1.x, a1.y, a1.z, a1.w};
            float bb[4] = {bv.x, bv.y, bv.z, bv.w};
#pragma unroll
            for (int i = 0; i < 8; i++)
#pragma unroll
                for (int j = 0; j < 4; j++) acc[i][j] = fmaf(a[i], bb[j], acc[i][j]);
        }
        __syncthreads();
    }

    int ncol = jw0 + tx * 4;
    float bd[4];
#pragma unroll
    for (int j = 0; j < 4; j++) bd[j] = b_dt[ncol + j];
    int c2 = ncol >> 2;
#pragma unroll
    for (int i = 0; i < 8; i++) {
        int m = m0 + ty * 8 + i;
        int b = m >> 12;
        int l = m & 4095;
        int ih = l >> 6;
        int iw = l & 63;
        const float* xb = x + (((b * 48 + c2) * 128 + ih * 2) * 128 + iw * 2);
        float uvals[4];
        uvals[0] = xb[0];
        uvals[1] = xb[1];
        uvals[2] = xb[128];
        uvals[3] = xb[129];
#pragma unroll
        for (int j = 0; j < 4; j++) {
            int dfeat = ncol + j;
            float lin = acc[i][j] + bd[j];
            float dt  = softplus_f(lin);
            float del = softplus_f(dt + bd[j]);
            float u   = uvals[j];
            int o = (b * 192 + dfeat) * LSEQ + l;
            g_dd[o] = make_float2(del, del * u);
            g_uT[o] = u;
        }
    }
}

// ---------------- K2: selective scan ----------------
// 128 blocks x 288 threads (9 warps). Block covers 3 d's (b = blk>>6, dbase = (blk&63)*3).
// warp w: dl = w/3, g = w%3; lane owns state pair n = g*64 + 2*lane for d = dbase+dl.
// Reduce is two-stage, all 288 threads active in stage 1.
#define CH   32
#define PR   108

__global__ void __launch_bounds__(288, 1)
scan_kernel(const float* __restrict__ A_log, const float* __restrict__ Dp,
            float* __restrict__ out) {
    extern __shared__ __align__(16) float S[];
    float*  BCf  = S;                      // [2][CH*384] = 24576
    float*  P    = S + 24576;              // [96][PR] = 10368
    float*  PS   = P + 10368;              // [96*3] = 288 (+pad)
    float2* DDsm = (float2*)(PS + 304);    // [2][3][CH] = 192 float2 = 384 f
    float*  Usm  = (float*)(DDsm + 192);   // [2][96] = 192
    float*  Dpsm = Usm + 192;              // [3]+pad

    int tid  = threadIdx.x;
    int w    = tid >> 5;
    int lane = tid & 31;
    int dl   = w / 3;          // d_local 0..2
    int g    = w - dl * 3;     // state group 0..2
    int b = blockIdx.x >> 6;
    int dbase = (blockIdx.x & 63) * 3;
    int d = dbase + dl;

    int n0 = g * 64 + 2 * lane;
    float A20 = -expf(A_log[d * 192 + n0])     * LOG2E;
    float A21 = -expf(A_log[d * 192 + n0 + 1]) * LOG2E;
    float h0 = 0.0f, h1 = 0.0f;
    if (tid < 3) Dpsm[tid] = Dp[dbase + tid];
    const float SILU1 = 0.73105857863000489f;

    // stage-1 reduce assignment: seg = tid/96, row = tid%96 (warp-uniform seg, consecutive rows)
    int s1seg = tid / 96;
    int s1row = tid - s1seg * 96;

    const float* BCsrc = (const float*)(g_BC + b * LSEQ * 192);

    // prologue: chunk 0
    {
#pragma unroll
        for (int q = 0; q < 10; q++) {
            int off = (tid + q * 288) * 4;
            cp16(BCf + off, BCsrc + off);
        }
        if (tid < 192) {
            int off = (tid + 2880) * 4;
            cp16(BCf + off, BCsrc + off);
        }
        if (tid < 24) {
            int du_ = tid >> 3, q = tid & 7;
            const float* usrc = g_uT + (b * 192 + dbase + du_) * LSEQ;
            cp16(Usm + du_ * 32 + q * 4, usrc + q * 4);
        }
        cp_commit();
        if (w >= 6) {   // warps 6..8 load DD chunk 0 for d_local = w-6
            int dd_l = w - 6;
            DDsm[dd_l * CH + lane] = g_dd[(b * 192 + dbase + dd_l) * LSEQ + lane];
        }
        cp_wait0();
    }
    __syncthreads();

    const int NCHUNK = LSEQ / CH;
    for (int c = 0; c < NCHUNK; c++) {
        int l0  = c * CH;
        int buf = c & 1;

        float2 ddn = make_float2(0.f, 0.f);
        if (c + 1 < NCHUNK) {
            const float* bsrc = BCsrc + (l0 + CH) * 384;
            float* bdst = BCf + (buf ^ 1) * 12288;
#pragma unroll
            for (int q = 0; q < 10; q++) {
                int off = (tid + q * 288) * 4;
                cp16(bdst + off, bsrc + off);
            }
            if (tid < 192) {
                int off = (tid + 2880) * 4;
                cp16(bdst + off, bsrc + off);
            }
            if (tid < 24) {
                int du_ = tid >> 3, q = tid & 7;
                const float* usrc = g_uT + (b * 192 + dbase + du_) * LSEQ + l0 + CH;
                cp16(Usm + (buf ^ 1) * 96 + du_ * 32 + q * 4, usrc + q * 4);
            }
            cp_commit();
            if (w >= 6) {
                int dd_l = w - 6;
                ddn = g_dd[(b * 192 + dbase + dd_l) * LSEQ + l0 + CH + lane];
            }
        }

        // ---- compute 32 steps ----
        {
            const float4* bcp = (const float4*)(BCf + buf * 12288) + g * 32 + lane;
            const float2* DDc = DDsm + buf * 96 + dl * CH;
            float* Pw = P + (dl * 32) * PR + g * 36 + lane;
#pragma unroll 4
            for (int s = 0; s < CH; s++) {
                float2 dd = DDc[s];
                float4 bc = bcp[s * 96];
                float e0 = ex2f(dd.x * A20);
                float e1 = ex2f(dd.x * A21);
                h0 = fmaf(e0, h0, dd.y * bc.x);
                h1 = fmaf(e1, h1, dd.y * bc.z);
                float acc = fmaf(h0, bc.y, h1 * bc.w);
                Pw[s * PR] = acc;
            }
        }
        __syncthreads();

        // ---- reduce stage 1: ALL 288 threads, one 32-float segment each ----
        {
            const float* Ps = P + s1row * PR + s1seg * 36;
            float4 q0 = *(const float4*)&Ps[0];
            float4 q1 = *(const float4*)&Ps[4];
            float4 q2 = *(const float4*)&Ps[8];
            float4 q3 = *(const float4*)&Ps[12];
            float4 q4 = *(const float4*)&Ps[16];
            float4 q5 = *(const float4*)&Ps[20];
            float4 q6 = *(const float4*)&Ps[24];
            float4 q7 = *(const float4*)&Ps[28];
            float s0 = (q0.x + q0.y) + (q0.z + q0.w);
            float s1 = (q1.x + q1.y) + (q1.z + q1.w);
            float s2 = (q2.x + q2.y) + (q2.z + q2.w);
            float s3 = (q3.x + q3.y) + (q3.z + q3.w);
            float s4 = (q4.x + q4.y) + (q4.z + q4.w);
            float s5 = (q5.x + q5.y) + (q5.z + q5.w);
            float s6 = (q6.x + q6.y) + (q6.z + q6.w);
            float s7 = (q7.x + q7.y) + (q7.z + q7.w);
            PS[s1row * 3 + s1seg] = ((s0 + s1) + (s2 + s3)) + ((s4 + s5) + (s6 + s7));
        }
        __syncthreads();

        // ---- reduce stage 2 + epilogue (tid<96); DD store next chunk (warps 6-8) ----
        if (tid < 96) {
            float sum = PS[tid * 3] + PS[tid * 3 + 1] + PS[tid * 3 + 2];
            int rdl = tid >> 5;
            int s   = tid & 31;
            float u   = Usm[buf * 96 + tid];
            float val = (sum + Dpsm[rdl] * u) * SILU1;

            int dd_ = dbase + rdl;
            int l = l0 + s;
            int flat = dd_ * LSEQ + l;
            int i1   = flat / 12288;
            int rem  = flat - i1 * 12288;
            int i2   = rem / 192;
            int r2   = rem - i2 * 192;
            int i3   = r2 >> 2;
            int i4   = (r2 >> 1) & 1;
            int i5   = r2 & 1;
            out[((b * 48 + i3) * 128 + i1 * 2 + i4) * 128 + i2 * 2 + i5] = val;
        } else if (w >= 6 && c + 1 < NCHUNK) {
            int dd_l = w - 6;
            DDsm[(buf ^ 1) * 96 + dd_l * CH + lane] = ddn;
        }

        cp_wait0();
        __syncthreads();
    }
}

// ---------------- launch ----------------
extern "C" void kernel_launch(void* const* d_in, const int* in_sizes, int n_in,
                              void* d_out, int out_size) {
    (void)in_sizes; (void)n_in; (void)out_size;
    const float* x     = (const float*)d_in[0];
    const float* A_log = (const float*)d_in[1];
    const float* Dp    = (const float*)d_in[2];
    const float* W_B   = (const float*)d_in[3];
    const float* b_B   = (const float*)d_in[4];
    const float* W_C   = (const float*)d_in[5];
    const float* b_C   = (const float*)d_in[6];
    const float* W_dt  = (const float*)d_in[7];
    const float* b_dt  = (const float*)d_in[8];
    float* out = (float*)d_out;

    // smem floats: BC 24576 + P 10368 + PS 304 + DD 384 + U 192 + Dp 4
    int smem = (24576 + 10368 + 304 + 384 + 192 + 4) * (int)sizeof(float);
    static int attr_set = 0;
    if (!attr_set) {
        cudaFuncSetAttribute(scan_kernel, cudaFuncAttributeMaxDynamicSharedMemorySize, smem);
        attr_set = 1;
    }

    dim3 gbc(64, 3);
    projBC_kernel<<<gbc, 256>>>(x, W_B, b_B, W_C, b_C);
    dim3 gdt(64, 3);
    projDT_kernel<<<gdt, 256>>>(x, W_dt, b_dt);
    scan_kernel<<<128, 288, smem>>>(A_log, Dp, out);
}

// round 13
// speedup vs baseline: 1.1857x; 1.1857x over previous
#include <cuda_runtime.h>
#include <math.h>

#define LSEQ 4096
#define DD   192
#define BB   2
#define TOT  (BB*LSEQ*DD)
#define LOG2E 1.4426950408889634f

// ---------------- scratch ----------------
__device__ __align__(16) float2 g_BC[TOT];   // [b][l][n] -> (B, C)
__device__ __align__(16) float2 g_dd[TOT];   // [b][d][l] -> (delta, delta*u)
__device__ __align__(16) float  g_uT[TOT];   // [b][d][l]

// ---------------- helpers ----------------
__device__ __forceinline__ float ex2f(float x) {
    float y;
    asm("ex2.approx.ftz.f32 %0, %1;" : "=f"(y) : "f"(x));
    return y;
}
__device__ __forceinline__ float softplus_f(float x) {
    if (x > 20.0f) return x;
    return log1pf(expf(x));
}
__device__ __forceinline__ void cp16(float* smem_dst, const float* gmem_src) {
    unsigned s = (unsigned)__cvta_generic_to_shared(smem_dst);
    asm volatile("cp.async.cg.shared.global [%0], [%1], 16;\n" :: "r"(s), "l"(gmem_src));
}
__device__ __forceinline__ void cp_commit() { asm volatile("cp.async.commit_group;\n" ::: "memory"); }
__device__ __forceinline__ void cp_wait0()  { asm volatile("cp.async.wait_group 0;\n" ::: "memory"); }

// ---------------- K1a: fused tokenize + B&C projections ----------------
__global__ void projBC_kernel(const float* __restrict__ x,
                              const float* __restrict__ W_B, const float* __restrict__ b_B,
                              const float* __restrict__ W_C, const float* __restrict__ b_C) {
    __shared__ __align__(16) float As[16][128];
    __shared__ __align__(16) float Bs[16][64];
    __shared__ __align__(16) float Cs[16][64];

    int tid = threadIdx.x;
    int tx = tid & 15;
    int ty = tid >> 4;
    int m0 = blockIdx.x * 128;
    int jw0 = blockIdx.y * 64;

    float accB[8][4], accC[8][4];
#pragma unroll
    for (int i = 0; i < 8; i++)
#pragma unroll
        for (int j = 0; j < 4; j++) { accB[i][j] = 0.0f; accC[i][j] = 0.0f; }

    for (int kt = 0; kt < 12; kt++) {
        int k0 = kt * 16;
#pragma unroll
        for (int r = 0; r < 2; r++) {
            int idx  = tid + r * 256;
            int mrow = idx >> 2;
            int kq   = idx & 3;
            int m = m0 + mrow;
            int b = m >> 12;
            int l = m & 4095;
            int ih = l >> 6;
            int iw = l & 63;
            int c  = (k0 >> 2) + kq;
            const float* xb = x + (((b * 48 + c) * 128 + ih * 2) * 128 + iw * 2);
            float2 v01 = *(const float2*)xb;
            float2 v23 = *(const float2*)(xb + 128);
            As[kq * 4 + 0][mrow] = v01.x;
            As[kq * 4 + 1][mrow] = v01.y;
            As[kq * 4 + 2][mrow] = v23.x;
            As[kq * 4 + 3][mrow] = v23.y;
        }
        {
            int jrow = tid >> 2;
            int kq   = tid & 3;
            float4 vb = *(const float4*)&W_B[(jw0 + jrow) * 192 + k0 + kq * 4];
            float4 vc = *(const float4*)&W_C[(jw0 + jrow) * 192 + k0 + kq * 4];
            Bs[kq * 4 + 0][jrow] = vb.x; Bs[kq * 4 + 1][jrow] = vb.y;
            Bs[kq * 4 + 2][jrow] = vb.z; Bs[kq * 4 + 3][jrow] = vb.w;
            Cs[kq * 4 + 0][jrow] = vc.x; Cs[kq * 4 + 1][jrow] = vc.y;
            Cs[kq * 4 + 2][jrow] = vc.z; Cs[kq * 4 + 3][jrow] = vc.w;
        }
        __syncthreads();
#pragma unroll
        for (int kk = 0; kk < 16; kk++) {
            float4 a0 = *(const float4*)&As[kk][ty * 8];
            float4 a1 = *(const float4*)&As[kk][ty * 8 + 4];
            float4 bv = *(const float4*)&Bs[kk][tx * 4];
            float4 cv = *(const float4*)&Cs[kk][tx * 4];
            float a[8] = {a0.x, a0.y, a0.z, a0.w, a1.x, a1.y, a1.z, a1.w};
            float bb[4] = {bv.x, bv.y, bv.z, bv.w};
            float cc[4] = {cv.x, cv.y, cv.z, cv.w};
#pragma unroll
            for (int i = 0; i < 8; i++)
#pragma unroll
                for (int j = 0; j < 4; j++) {
                    accB[i][j] = fmaf(a[i], bb[j], accB[i][j]);
                    accC[i][j] = fmaf(a[i], cc[j], accC[i][j]);
                }
        }
        __syncthreads();
    }

    int ncol = jw0 + tx * 4;
    float4 bB4 = *(const float4*)&b_B[ncol];
    float4 bC4 = *(const float4*)&b_C[ncol];
#pragma unroll
    for (int i = 0; i < 8; i++) {
        int m = m0 + ty * 8 + i;
        float4 o01, o23;
        o01.x = accB[i][0] + bB4.x; o01.y = accC[i][0] + bC4.x;
        o01.z = accB[i][1] + bB4.y; o01.w = accC[i][1] + bC4.y;
        o23.x = accB[i][2] + bB4.z; o23.y = accC[i][2] + bC4.z;
        o23.z = accB[i][3] + bB4.w; o23.w = accC[i][3] + bC4.w;
        *(float4*)&g_BC[m * 192 + ncol]     = o01;
        *(float4*)&g_BC[m * 192 + ncol + 2] = o23;
    }
}

// ---------------- K1b: fused tokenize + dt projection ----------------
__global__ void projDT_kernel(const float* __restrict__ x,
                              const float* __restrict__ W_dt, const float* __restrict__ b_dt) {
    __shared__ __align__(16) float As[16][128];
    __shared__ __align__(16) float Bs[16][64];

    int tid = threadIdx.x;
    int tx = tid & 15;
    int ty = tid >> 4;
    int m0 = blockIdx.x * 128;
    int jw0 = blockIdx.y * 64;

    float acc[8][4];
#pragma unroll
    for (int i = 0; i < 8; i++)
#pragma unroll
        for (int j = 0; j < 4; j++) acc[i][j] = 0.0f;

    for (int kt = 0; kt < 12; kt++) {
        int k0 = kt * 16;
#pragma unroll
        for (int r = 0; r < 2; r++) {
            int idx  = tid + r * 256;
            int mrow = idx >> 2;
            int kq   = idx & 3;
            int m = m0 + mrow;
            int b = m >> 12;
            int l = m & 4095;
            int ih = l >> 6;
            int iw = l & 63;
            int c  = (k0 >> 2) + kq;
            const float* xb = x + (((b * 48 + c) * 128 + ih * 2) * 128 + iw * 2);
            float2 v01 = *(const float2*)xb;
            float2 v23 = *(const float2*)(xb + 128);
            As[kq * 4 + 0][mrow] = v01.x;
            As[kq * 4 + 1][mrow] = v01.y;
            As[kq * 4 + 2][mrow] = v23.x;
            As[kq * 4 + 3][mrow] = v23.y;
        }
        {
            int jrow = tid >> 2;
            int kq   = tid & 3;
            float4 v = *(const float4*)&W_dt[(jw0 + jrow) * 192 + k0 + kq * 4];
            Bs[kq * 4 + 0][jrow] = v.x; Bs[kq * 4 + 1][jrow] = v.y;
            Bs[kq * 4 + 2][jrow] = v.z; Bs[kq * 4 + 3][jrow] = v.w;
        }
        __syncthreads();
#pragma unroll
        for (int kk = 0; kk < 16; kk++) {
            float4 a0 = *(const float4*)&As[kk][ty * 8];
            float4 a1 = *(const float4*)&As[kk][ty * 8 + 4];
            float4 bv = *(const float4*)&Bs[kk][tx * 4];
            float a[8] = {a0.x, a0.y, a0.z, a0.w, a1.x, a1.y, a1.z, a1.w};
            float bb[4] = {bv.x, bv.y, bv.z, bv.w};
#pragma unroll
            for (int i = 0; i < 8; i++)
#pragma unroll
                for (int j = 0; j < 4; j++) acc[i][j] = fmaf(a[i], bb[j], acc[i][j]);
        }
        __syncthreads();
    }

    int ncol = jw0 + tx * 4;
    float bd[4];
#pragma unroll
    for (int j = 0; j < 4; j++) bd[j] = b_dt[ncol + j];
    int c2 = ncol >> 2;
#pragma unroll
    for (int i = 0; i < 8; i++) {
        int m = m0 + ty * 8 + i;
        int b = m >> 12;
        int l = m & 4095;
        int ih = l >> 6;
        int iw = l & 63;
        const float* xb = x + (((b * 48 + c2) * 128 + ih * 2) * 128 + iw * 2);
        float uvals[4];
        uvals[0] = xb[0];
        uvals[1] = xb[1];
        uvals[2] = xb[128];
        uvals[3] = xb[129];
#pragma unroll
        for (int j = 0; j < 4; j++) {
            int dfeat = ncol + j;
            float lin = acc[i][j] + bd[j];
            float dt  = softplus_f(lin);
            float del = softplus_f(dt + bd[j]);
            float u   = uvals[j];
            int o = (b * 192 + dfeat) * LSEQ + l;
            g_dd[o] = make_float2(del, del * u);
            g_uT[o] = u;
        }
    }
}

// ---------------- K2: selective scan ----------------
// 128 blocks x 288 threads (9 warps). Block covers 3 d's (b = blk>>6, dbase = (blk&63)*3).
// warp w: dl = w/3, g = w%3; lane owns state pair n = g*64 + 2*lane for d = dbase+dl.
// Compute phase: two 16-step REGISTER-accumulated bursts (no STS inside the load/math
// loop -> compiler can hoist all LDS; only loop-carried dep is the 4-cyc h fma chain).
#define CH   32
#define PR   108

__global__ void __launch_bounds__(288, 1)
scan_kernel(const float* __restrict__ A_log, const float* __restrict__ Dp,
            float* __restrict__ out) {
    extern __shared__ __align__(16) float S[];
    float*  BCf  = S;                      // [2][CH*384] = 24576
    float*  P    = S + 24576;              // [96][PR] = 10368
    float*  PS   = P + 10368;              // [96*3] = 288 (+pad)
    float2* DDsm = (float2*)(PS + 304);    // [2][3][CH] = 192 float2 = 384 f
    float*  Usm  = (float*)(DDsm + 192);   // [2][96] = 192
    float*  Dpsm = Usm + 192;              // [3]+pad

    int tid  = threadIdx.x;
    int w    = tid >> 5;
    int lane = tid & 31;
    int dl   = w / 3;          // d_local 0..2
    int g    = w - dl * 3;     // state group 0..2
    int b = blockIdx.x >> 6;
    int dbase = (blockIdx.x & 63) * 3;
    int d = dbase + dl;

    int n0 = g * 64 + 2 * lane;
    float A20 = -expf(A_log[d * 192 + n0])     * LOG2E;
    float A21 = -expf(A_log[d * 192 + n0 + 1]) * LOG2E;
    float h0 = 0.0f, h1 = 0.0f;
    if (tid < 3) Dpsm[tid] = Dp[dbase + tid];
    const float SILU1 = 0.73105857863000489f;

    // stage-1 reduce assignment: seg = tid/96, row = tid%96
    int s1seg = tid / 96;
    int s1row = tid - s1seg * 96;

    const float* BCsrc = (const float*)(g_BC + b * LSEQ * 192);

    // prologue: chunk 0
    {
#pragma unroll
        for (int q = 0; q < 10; q++) {
            int off = (tid + q * 288) * 4;
            cp16(BCf + off, BCsrc + off);
        }
        if (tid < 192) {
            int off = (tid + 2880) * 4;
            cp16(BCf + off, BCsrc + off);
        }
        if (tid < 24) {
            int du_ = tid >> 3, q = tid & 7;
            const float* usrc = g_uT + (b * 192 + dbase + du_) * LSEQ;
            cp16(Usm + du_ * 32 + q * 4, usrc + q * 4);
        }
        cp_commit();
        if (w >= 6) {   // warps 6..8 load DD chunk 0 for d_local = w-6
            int dd_l = w - 6;
            DDsm[dd_l * CH + lane] = g_dd[(b * 192 + dbase + dd_l) * LSEQ + lane];
        }
        cp_wait0();
    }
    __syncthreads();

    const int NCHUNK = LSEQ / CH;
    for (int c = 0; c < NCHUNK; c++) {
        int l0  = c * CH;
        int buf = c & 1;

        float2 ddn = make_float2(0.f, 0.f);
        if (c + 1 < NCHUNK) {
            const float* bsrc = BCsrc + (l0 + CH) * 384;
            float* bdst = BCf + (buf ^ 1) * 12288;
#pragma unroll
            for (int q = 0; q < 10; q++) {
                int off = (tid + q * 288) * 4;
                cp16(bdst + off, bsrc + off);
            }
            if (tid < 192) {
                int off = (tid + 2880) * 4;
                cp16(bdst + off, bsrc + off);
            }
            if (tid < 24) {
                int du_ = tid >> 3, q = tid & 7;
                const float* usrc = g_uT + (b * 192 + dbase + du_) * LSEQ + l0 + CH;
                cp16(Usm + (buf ^ 1) * 96 + du_ * 32 + q * 4, usrc + q * 4);
            }
            cp_commit();
            if (w >= 6) {
                int dd_l = w - 6;
                ddn = g_dd[(b * 192 + dbase + dd_l) * LSEQ + l0 + CH + lane];
            }
        }

        // ---- compute 32 steps: 2 register-accumulated 16-step bursts ----
        {
            const float4* bcp = (const float4*)(BCf + buf * 12288) + g * 32 + lane;
            const float2* DDc = DDsm + buf * 96 + dl * CH;
            float* Pw = P + (dl * 32) * PR + g * 36 + lane;
#pragma unroll
            for (int hf = 0; hf < 2; hf++) {
                float acc[16];
#pragma unroll
                for (int s = 0; s < 16; s++) {
                    float2 dd = DDc[hf * 16 + s];
                    float4 bc = bcp[(hf * 16 + s) * 96];
                    float e0 = ex2f(dd.x * A20);
                    float e1 = ex2f(dd.x * A21);
                    h0 = fmaf(e0, h0, dd.y * bc.x);
                    h1 = fmaf(e1, h1, dd.y * bc.z);
                    acc[s] = fmaf(h0, bc.y, h1 * bc.w);
                }
#pragma unroll
                for (int s = 0; s < 16; s++)
                    Pw[(hf * 16 + s) * PR] = acc[s];
            }
        }
        __syncthreads();

        // ---- reduce stage 1: ALL 288 threads, one 32-float segment each ----
        {
            const float* Ps = P + s1row * PR + s1seg * 36;
            float4 q0 = *(const float4*)&Ps[0];
            float4 q1 = *(const float4*)&Ps[4];
            float4 q2 = *(const float4*)&Ps[8];
            float4 q3 = *(const float4*)&Ps[12];
            float4 q4 = *(const float4*)&Ps[16];
            float4 q5 = *(const float4*)&Ps[20];
            float4 q6 = *(const float4*)&Ps[24];
            float4 q7 = *(const float4*)&Ps[28];
            float s0 = (q0.x + q0.y) + (q0.z + q0.w);
            float s1 = (q1.x + q1.y) + (q1.z + q1.w);
            float s2 = (q2.x + q2.y) + (q2.z + q2.w);
            float s3 = (q3.x + q3.y) + (q3.z + q3.w);
            float s4 = (q4.x + q4.y) + (q4.z + q4.w);
            float s5 = (q5.x + q5.y) + (q5.z + q5.w);
            float s6 = (q6.x + q6.y) + (q6.z + q6.w);
            float s7 = (q7.x + q7.y) + (q7.z + q7.w);
            PS[s1row * 3 + s1seg] = ((s0 + s1) + (s2 + s3)) + ((s4 + s5) + (s6 + s7));
        }
        __syncthreads();

        // ---- reduce stage 2 + epilogue (tid<96); DD store next chunk (warps 6-8) ----
        if (tid < 96) {
            float sum = PS[tid * 3] + PS[tid * 3 + 1] + PS[tid * 3 + 2];
            int rdl = tid >> 5;
            int s   = tid & 31;
            float u   = Usm[buf * 96 + tid];
            float val = (sum + Dpsm[rdl] * u) * SILU1;

            int dd_ = dbase + rdl;
            int l = l0 + s;
            int flat = dd_ * LSEQ + l;
            int i1   = flat / 12288;
            int rem  = flat - i1 * 12288;
            int i2   = rem / 192;
            int r2   = rem - i2 * 192;
            int i3   = r2 >> 2;
            int i4   = (r2 >> 1) & 1;
            int i5   = r2 & 1;
            out[((b * 48 + i3) * 128 + i1 * 2 + i4) * 128 + i2 * 2 + i5] = val;
        } else if (w >= 6 && c + 1 < NCHUNK) {
            int dd_l = w - 6;
            DDsm[(buf ^ 1) * 96 + dd_l * CH + lane] = ddn;
        }

        cp_wait0();
        __syncthreads();
    }
}

// ---------------- launch ----------------
extern "C" void kernel_launch(void* const* d_in, const int* in_sizes, int n_in,
                              void* d_out, int out_size) {
    (void)in_sizes; (void)n_in; (void)out_size;
    const float* x     = (const float*)d_in[0];
    const float* A_log = (const float*)d_in[1];
    const float* Dp    = (const float*)d_in[2];
    const float* W_B   = (const float*)d_in[3];
    const float* b_B   = (const float*)d_in[4];
    const float* W_C   = (const float*)d_in[5];
    const float* b_C   = (const float*)d_in[6];
    const float* W_dt  = (const float*)d_in[7];
    const float* b_dt  = (const float*)d_in[8];
    float* out = (float*)d_out;

    // smem floats: BC 24576 + P 10368 + PS 304 + DD 384 + U 192 + Dp 4
    int smem = (24576 + 10368 + 304 + 384 + 192 + 4) * (int)sizeof(float);
    static int attr_set = 0;
    if (!attr_set) {
        cudaFuncSetAttribute(scan_kernel, cudaFuncAttributeMaxDynamicSharedMemorySize, smem);
        attr_set = 1;
    }

    dim3 gbc(64, 3);
    projBC_kernel<<<gbc, 256>>>(x, W_B, b_B, W_C, b_C);
    dim3 gdt(64, 3);
    projDT_kernel<<<gdt, 256>>>(x, W_dt, b_dt);
    scan_kernel<<<128, 288, smem>>>(A_log, Dp, out);
}

// round 14
// speedup vs baseline: 1.2316x; 1.0387x over previous
#include <cuda_runtime.h>
#include <math.h>

#define LSEQ 4096
#define DD   192
#define BB   2
#define TOT  (BB*LSEQ*DD)
#define LOG2E 1.4426950408889634f

// ---------------- scratch ----------------
__device__ __align__(16) float2 g_BC[TOT];   // [b][l][n] -> (B, C)
__device__ __align__(16) float2 g_dd[TOT];   // [b][d][l] -> (delta, delta*u)
__device__ __align__(16) float  g_uT[TOT];   // [b][d][l]

// ---------------- helpers ----------------
__device__ __forceinline__ float ex2f(float x) {
    float y;
    asm("ex2.approx.ftz.f32 %0, %1;" : "=f"(y) : "f"(x));
    return y;
}
__device__ __forceinline__ float softplus_f(float x) {
    if (x > 20.0f) return x;
    return log1pf(expf(x));
}
__device__ __forceinline__ void cp16(float* smem_dst, const float* gmem_src) {
    unsigned s = (unsigned)__cvta_generic_to_shared(smem_dst);
    asm volatile("cp.async.cg.shared.global [%0], [%1], 16;\n" :: "r"(s), "l"(gmem_src));
}
__device__ __forceinline__ void cp_commit() { asm volatile("cp.async.commit_group;\n" ::: "memory"); }
__device__ __forceinline__ void cp_wait0()  { asm volatile("cp.async.wait_group 0;\n" ::: "memory"); }

// ---------------- K1a: fused tokenize + B&C projections (unchanged) ----------------
__global__ void projBC_kernel(const float* __restrict__ x,
                              const float* __restrict__ W_B, const float* __restrict__ b_B,
                              const float* __restrict__ W_C, const float* __restrict__ b_C) {
    __shared__ __align__(16) float As[16][128];
    __shared__ __align__(16) float Bs[16][64];
    __shared__ __align__(16) float Cs[16][64];

    int tid = threadIdx.x;
    int tx = tid & 15;
    int ty = tid >> 4;
    int m0 = blockIdx.x * 128;
    int jw0 = blockIdx.y * 64;

    float accB[8][4], accC[8][4];
#pragma unroll
    for (int i = 0; i < 8; i++)
#pragma unroll
        for (int j = 0; j < 4; j++) { accB[i][j] = 0.0f; accC[i][j] = 0.0f; }

    for (int kt = 0; kt < 12; kt++) {
        int k0 = kt * 16;
#pragma unroll
        for (int r = 0; r < 2; r++) {
            int idx  = tid + r * 256;
            int mrow = idx >> 2;
            int kq   = idx & 3;
            int m = m0 + mrow;
            int b = m >> 12;
            int l = m & 4095;
            int ih = l >> 6;
            int iw = l & 63;
            int c  = (k0 >> 2) + kq;
            const float* xb = x + (((b * 48 + c) * 128 + ih * 2) * 128 + iw * 2);
            float2 v01 = *(const float2*)xb;
            float2 v23 = *(const float2*)(xb + 128);
            As[kq * 4 + 0][mrow] = v01.x;
            As[kq * 4 + 1][mrow] = v01.y;
            As[kq * 4 + 2][mrow] = v23.x;
            As[kq * 4 + 3][mrow] = v23.y;
        }
        {
            int jrow = tid >> 2;
            int kq   = tid & 3;
            float4 vb = *(const float4*)&W_B[(jw0 + jrow) * 192 + k0 + kq * 4];
            float4 vc = *(const float4*)&W_C[(jw0 + jrow) * 192 + k0 + kq * 4];
            Bs[kq * 4 + 0][jrow] = vb.x; Bs[kq * 4 + 1][jrow] = vb.y;
            Bs[kq * 4 + 2][jrow] = vb.z; Bs[kq * 4 + 3][jrow] = vb.w;
            Cs[kq * 4 + 0][jrow] = vc.x; Cs[kq * 4 + 1][jrow] = vc.y;
            Cs[kq * 4 + 2][jrow] = vc.z; Cs[kq * 4 + 3][jrow] = vc.w;
        }
        __syncthreads();
#pragma unroll
        for (int kk = 0; kk < 16; kk++) {
            float4 a0 = *(const float4*)&As[kk][ty * 8];
            float4 a1 = *(const float4*)&As[kk][ty * 8 + 4];
            float4 bv = *(const float4*)&Bs[kk][tx * 4];
            float4 cv = *(const float4*)&Cs[kk][tx * 4];
            float a[8] = {a0.x, a0.y, a0.z, a0.w, a1.x, a1.y, a1.z, a1.w};
            float bb[4] = {bv.x, bv.y, bv.z, bv.w};
            float cc[4] = {cv.x, cv.y, cv.z, cv.w};
#pragma unroll
            for (int i = 0; i < 8; i++)
#pragma unroll
                for (int j = 0; j < 4; j++) {
                    accB[i][j] = fmaf(a[i], bb[j], accB[i][j]);
                    accC[i][j] = fmaf(a[i], cc[j], accC[i][j]);
                }
        }
        __syncthreads();
    }

    int ncol = jw0 + tx * 4;
    float4 bB4 = *(const float4*)&b_B[ncol];
    float4 bC4 = *(const float4*)&b_C[ncol];
#pragma unroll
    for (int i = 0; i < 8; i++) {
        int m = m0 + ty * 8 + i;
        float4 o01, o23;
        o01.x = accB[i][0] + bB4.x; o01.y = accC[i][0] + bC4.x;
        o01.z = accB[i][1] + bB4.y; o01.w = accC[i][1] + bC4.y;
        o23.x = accB[i][2] + bB4.z; o23.y = accC[i][2] + bC4.z;
        o23.z = accB[i][3] + bB4.w; o23.w = accC[i][3] + bC4.w;
        *(float4*)&g_BC[m * 192 + ncol]     = o01;
        *(float4*)&g_BC[m * 192 + ncol + 2] = o23;
    }
}

// ---------------- K1b: fused tokenize + dt projection (unchanged) ----------------
__global__ void projDT_kernel(const float* __restrict__ x,
                              const float* __restrict__ W_dt, const float* __restrict__ b_dt) {
    __shared__ __align__(16) float As[16][128];
    __shared__ __align__(16) float Bs[16][64];

    int tid = threadIdx.x;
    int tx = tid & 15;
    int ty = tid >> 4;
    int m0 = blockIdx.x * 128;
    int jw0 = blockIdx.y * 64;

    float acc[8][4];
#pragma unroll
    for (int i = 0; i < 8; i++)
#pragma unroll
        for (int j = 0; j < 4; j++) acc[i][j] = 0.0f;

    for (int kt = 0; kt < 12; kt++) {
        int k0 = kt * 16;
#pragma unroll
        for (int r = 0; r < 2; r++) {
            int idx  = tid + r * 256;
            int mrow = idx >> 2;
            int kq   = idx & 3;
            int m = m0 + mrow;
            int b = m >> 12;
            int l = m & 4095;
            int ih = l >> 6;
            int iw = l & 63;
            int c  = (k0 >> 2) + kq;
            const float* xb = x + (((b * 48 + c) * 128 + ih * 2) * 128 + iw * 2);
            float2 v01 = *(const float2*)xb;
            float2 v23 = *(const float2*)(xb + 128);
            As[kq * 4 + 0][mrow] = v01.x;
            As[kq * 4 + 1][mrow] = v01.y;
            As[kq * 4 + 2][mrow] = v23.x;
            As[kq * 4 + 3][mrow] = v23.y;
        }
        {
            int jrow = tid >> 2;
            int kq   = tid & 3;
            float4 v = *(const float4*)&W_dt[(jw0 + jrow) * 192 + k0 + kq * 4];
            Bs[kq * 4 + 0][jrow] = v.x; Bs[kq * 4 + 1][jrow] = v.y;
            Bs[kq * 4 + 2][jrow] = v.z; Bs[kq * 4 + 3][jrow] = v.w;
        }
        __syncthreads();
#pragma unroll
        for (int kk = 0; kk < 16; kk++) {
            float4 a0 = *(const float4*)&As[kk][ty * 8];
            float4 a1 = *(const float4*)&As[kk][ty * 8 + 4];
            float4 bv = *(const float4*)&Bs[kk][tx * 4];
            float a[8] = {a0.x, a0.y, a0.z, a0.w, a1.x, a1.y, a1.z, a1.w};
            float bb[4] = {bv.x, bv.y, bv.z, bv.w};
#pragma unroll
            for (int i = 0; i < 8; i++)
#pragma unroll
                for (int j = 0; j < 4; j++) acc[i][j] = fmaf(a[i], bb[j], acc[i][j]);
        }
        __syncthreads();
    }

    int ncol = jw0 + tx * 4;
    float bd[4];
#pragma unroll
    for (int j = 0; j < 4; j++) bd[j] = b_dt[ncol + j];
    int c2 = ncol >> 2;
#pragma unroll
    for (int i = 0; i < 8; i++) {
        int m = m0 + ty * 8 + i;
        int b = m >> 12;
        int l = m & 4095;
        int ih = l >> 6;
        int iw = l & 63;
        const float* xb = x + (((b * 48 + c2) * 128 + ih * 2) * 128 + iw * 2);
        float uvals[4];
        uvals[0] = xb[0];
        uvals[1] = xb[1];
        uvals[2] = xb[128];
        uvals[3] = xb[129];
#pragma unroll
        for (int j = 0; j < 4; j++) {
            int dfeat = ncol + j;
            float lin = acc[i][j] + bd[j];
            float dt  = softplus_f(lin);
            float del = softplus_f(dt + bd[j]);
            float u   = uvals[j];
            int o = (b * 192 + dfeat) * LSEQ + l;
            g_dd[o] = make_float2(del, del * u);
            g_uT[o] = u;
        }
    }
}

// ---------------- K2: selective scan ----------------
// 128 blocks x 288 threads (9 warps). Block covers 3 d's (b = blk>>6, dbase = (blk&63)*3).
// warp w: dl = w/3, g = w%3; lane owns state pair n = g*64 + 2*lane for d = dbase+dl.
// Per chunk: register compute (acc[32]) -> in-register butterfly reduce+transpose
// (31 shfl, lane l ends with step-l sum) -> 1 STS -> ONE barrier -> tid<96 sums 3 warps + STG.
#define CH   32

__global__ void __launch_bounds__(288, 1)
scan_kernel(const float* __restrict__ A_log, const float* __restrict__ Dp,
            float* __restrict__ out) {
    extern __shared__ __align__(16) float S[];
    float*  BCf  = S;                        // [2][CH*384] = 24576
    float*  PS3  = S + 24576;                // [2][3][96] = 576
    float2* DDsm = (float2*)(PS3 + 576);     // [2][3][32] float2 = 384 f
    float*  Dpsm = (float*)(DDsm + 192);     // [3]+pad

    int tid  = threadIdx.x;
    int w    = tid >> 5;
    int lane = tid & 31;
    int dl   = w / 3;          // d_local 0..2
    int g    = w - dl * 3;     // state group 0..2
    int b = blockIdx.x >> 6;
    int dbase = (blockIdx.x & 63) * 3;
    int d = dbase + dl;

    int n0 = g * 64 + 2 * lane;
    float A20 = -expf(A_log[d * 192 + n0])     * LOG2E;
    float A21 = -expf(A_log[d * 192 + n0 + 1]) * LOG2E;
    float h0 = 0.0f, h1 = 0.0f;
    if (tid < 3) Dpsm[tid] = Dp[dbase + tid];
    const float SILU1 = 0.73105857863000489f;

    // epilogue thread mapping (tid < 96): d_local = tid>>5, step = tid&31
    int edl = tid >> 5;
    int es  = tid & 31;
    const float* usrc = g_uT + (b * 192 + dbase + edl) * LSEQ + es;

    const float* BCsrc = (const float*)(g_BC + b * LSEQ * 192);

    float u_cur = 0.0f;
    // prologue: chunk 0
    {
        for (int t = tid; t < 3072; t += 288)
            cp16(BCf + t * 4, BCsrc + t * 4);
        cp_commit();
        if (tid < 96) u_cur = usrc[0];
        if (w >= 6)
            DDsm[(w - 6) * 32 + lane] = g_dd[(b * 192 + dbase + (w - 6)) * LSEQ + lane];
        cp_wait0();
    }
    __syncthreads();

    const int NCHUNK = LSEQ / CH;
    for (int c = 0; c < NCHUNK; c++) {
        int l0  = c * CH;
        int buf = c & 1;

        float2 ddn = make_float2(0.f, 0.f);
        float u_nxt = 0.0f;
        if (c + 1 < NCHUNK) {
            const float* bsrc = BCsrc + (l0 + CH) * 384;
            float* bdst = BCf + (buf ^ 1) * 12288;
            for (int t = tid; t < 3072; t += 288)
                cp16(bdst + t * 4, bsrc + t * 4);
            cp_commit();
            if (tid < 96) u_nxt = usrc[l0 + CH];
            if (w >= 6)
                ddn = g_dd[(b * 192 + dbase + (w - 6)) * LSEQ + l0 + CH + lane];
        }

        // ---- compute 32 steps into registers ----
        float acc[32];
        {
            const float4* bcp = (const float4*)(BCf + buf * 12288) + g * 32 + lane;
            const float2* DDc = DDsm + buf * 96 + dl * 32;
#pragma unroll
            for (int s = 0; s < CH; s++) {
                float2 dd = DDc[s];
                float4 bc = bcp[s * 96];
                float e0 = ex2f(dd.x * A20);
                float e1 = ex2f(dd.x * A21);
                h0 = fmaf(e0, h0, dd.y * bc.x);
                h1 = fmaf(e1, h1, dd.y * bc.z);
                acc[s] = fmaf(h0, bc.y, h1 * bc.w);
            }
        }

        // ---- in-register butterfly: reduce over lanes + transpose (lane l -> step l) ----
#pragma unroll
        for (int m = 16; m >= 1; m >>= 1) {
            bool hi = (lane & m) != 0;
#pragma unroll
            for (int j = 0; j < m; j++) {
                float send = hi ? acc[j] : acc[j + m];
                float recv = __shfl_xor_sync(0xffffffffu, send, m);
                float keep = hi ? acc[j + m] : acc[j];
                acc[j] = keep + recv;
            }
        }
        // acc[0] = sum over this warp's 64 states for step `lane`
        PS3[buf * 288 + g * 96 + dl * 32 + lane] = acc[0];

        if (w >= 6 && c + 1 < NCHUNK)
            DDsm[(buf ^ 1) * 96 + (w - 6) * 32 + lane] = ddn;

        cp_wait0();
        __syncthreads();

        // ---- cross-warp sum + epilogue (tid<96), overlaps next iteration's prefetch ----
        if (tid < 96) {
            int base = buf * 288 + tid;
            float sum = PS3[base] + PS3[base + 96] + PS3[base + 192];
            float val = (sum + Dpsm[edl] * u_cur) * SILU1;

            int dd_ = dbase + edl;
            int l = l0 + es;
            int flat = dd_ * LSEQ + l;
            int i1   = flat / 12288;
            int rem  = flat - i1 * 12288;
            int i2   = rem / 192;
            int r2   = rem - i2 * 192;
            int i3   = r2 >> 2;
            int i4   = (r2 >> 1) & 1;
            int i5   = r2 & 1;
            out[((b * 48 + i3) * 128 + i1 * 2 + i4) * 128 + i2 * 2 + i5] = val;
        }
        u_cur = u_nxt;
    }
}

// ---------------- launch ----------------
extern "C" void kernel_launch(void* const* d_in, const int* in_sizes, int n_in,
                              void* d_out, int out_size) {
    (void)in_sizes; (void)n_in; (void)out_size;
    const float* x     = (const float*)d_in[0];
    const float* A_log = (const float*)d_in[1];
    const float* Dp    = (const float*)d_in[2];
    const float* W_B   = (const float*)d_in[3];
    const float* b_B   = (const float*)d_in[4];
    const float* W_C   = (const float*)d_in[5];
    const float* b_C   = (const float*)d_in[6];
    const float* W_dt  = (const float*)d_in[7];
    const float* b_dt  = (const float*)d_in[8];
    float* out = (float*)d_out;

    // smem floats: BC 24576 + PS3 576 + DD 384 + Dp 4 = 25540 (~102KB)
    int smem = (24576 + 576 + 384 + 4) * (int)sizeof(float);
    static int attr_set = 0;
    if (!attr_set) {
        cudaFuncSetAttribute(scan_kernel, cudaFuncAttributeMaxDynamicSharedMemorySize, smem);
        attr_set = 1;
    }

    dim3 gbc(64, 3);
    projBC_kernel<<<gbc, 256>>>(x, W_B, b_B, W_C, b_C);
    dim3 gdt(64, 3);
    projDT_kernel<<<gdt, 256>>>(x, W_dt, b_dt);
    scan_kernel<<<128, 288, smem>>>(A_log, Dp, out);
}

// round 15
// speedup vs baseline: 1.3358x; 1.0845x over previous
#include <cuda_runtime.h>
#include <math.h>

#define LSEQ 4096
#define DD   192
#define BB   2
#define TOT  (BB*LSEQ*DD)
#define LOG2E 1.4426950408889634f

// ---------------- scratch ----------------
__device__ __align__(16) float2 g_BC[TOT];   // [b][l][n] -> (B, C)
__device__ __align__(16) float2 g_dd[TOT];   // [b][d][l] -> (delta, delta*u)
__device__ __align__(16) float  g_uT[TOT];   // [b][d][l]

// ---------------- helpers ----------------
__device__ __forceinline__ float ex2f(float x) {
    float y;
    asm("ex2.approx.ftz.f32 %0, %1;" : "=f"(y) : "f"(x));
    return y;
}
__device__ __forceinline__ float softplus_f(float x) {
    if (x > 20.0f) return x;
    return log1pf(expf(x));
}
__device__ __forceinline__ void cp16(float* smem_dst, const float* gmem_src) {
    unsigned s = (unsigned)__cvta_generic_to_shared(smem_dst);
    asm volatile("cp.async.cg.shared.global [%0], [%1], 16;\n" :: "r"(s), "l"(gmem_src));
}
__device__ __forceinline__ void cp_commit() { asm volatile("cp.async.commit_group;\n" ::: "memory"); }
__device__ __forceinline__ void cp_wait0()  { asm volatile("cp.async.wait_group 0;\n" ::: "memory"); }

// ---------------- K1: merged tokenize + all three projections ----------------
// blockIdx.y < 3: (B,C) interleaved output; blockIdx.y >= 3: dt path.
__global__ void proj_kernel(const float* __restrict__ x,
                            const float* __restrict__ W_B, const float* __restrict__ b_B,
                            const float* __restrict__ W_C, const float* __restrict__ b_C,
                            const float* __restrict__ W_dt, const float* __restrict__ b_dt) {
    __shared__ __align__(16) float As[16][128];
    __shared__ __align__(16) float Bs[16][64];
    __shared__ __align__(16) float Cs[16][64];

    int tid = threadIdx.x;
    int tx = tid & 15;
    int ty = tid >> 4;
    int m0 = blockIdx.x * 128;
    int by = blockIdx.y;
    bool isBC = (by < 3);
    int jw0 = (isBC ? by : by - 3) * 64;

    float accB[8][4], accC[8][4];
#pragma unroll
    for (int i = 0; i < 8; i++)
#pragma unroll
        for (int j = 0; j < 4; j++) { accB[i][j] = 0.0f; accC[i][j] = 0.0f; }

    for (int kt = 0; kt < 12; kt++) {
        int k0 = kt * 16;
#pragma unroll
        for (int r = 0; r < 2; r++) {
            int idx  = tid + r * 256;
            int mrow = idx >> 2;
            int kq   = idx & 3;
            int m = m0 + mrow;
            int b = m >> 12;
            int l = m & 4095;
            int ih = l >> 6;
            int iw = l & 63;
            int c  = (k0 >> 2) + kq;
            const float* xb = x + (((b * 48 + c) * 128 + ih * 2) * 128 + iw * 2);
            float2 v01 = *(const float2*)xb;
            float2 v23 = *(const float2*)(xb + 128);
            As[kq * 4 + 0][mrow] = v01.x;
            As[kq * 4 + 1][mrow] = v01.y;
            As[kq * 4 + 2][mrow] = v23.x;
            As[kq * 4 + 3][mrow] = v23.y;
        }
        {
            int jrow = tid >> 2;
            int kq   = tid & 3;
            const float* W1 = isBC ? W_B : W_dt;
            float4 vb = *(const float4*)&W1[(jw0 + jrow) * 192 + k0 + kq * 4];
            Bs[kq * 4 + 0][jrow] = vb.x; Bs[kq * 4 + 1][jrow] = vb.y;
            Bs[kq * 4 + 2][jrow] = vb.z; Bs[kq * 4 + 3][jrow] = vb.w;
            if (isBC) {
                float4 vc = *(const float4*)&W_C[(jw0 + jrow) * 192 + k0 + kq * 4];
                Cs[kq * 4 + 0][jrow] = vc.x; Cs[kq * 4 + 1][jrow] = vc.y;
                Cs[kq * 4 + 2][jrow] = vc.z; Cs[kq * 4 + 3][jrow] = vc.w;
            }
        }
        __syncthreads();
        if (isBC) {
#pragma unroll
            for (int kk = 0; kk < 16; kk++) {
                float4 a0 = *(const float4*)&As[kk][ty * 8];
                float4 a1 = *(const float4*)&As[kk][ty * 8 + 4];
                float4 bv = *(const float4*)&Bs[kk][tx * 4];
                float4 cv = *(const float4*)&Cs[kk][tx * 4];
                float a[8] = {a0.x, a0.y, a0.z, a0.w, a1.x, a1.y, a1.z, a1.w};
                float bb[4] = {bv.x, bv.y, bv.z, bv.w};
                float cc[4] = {cv.x, cv.y, cv.z, cv.w};
#pragma unroll
                for (int i = 0; i < 8; i++)
#pragma unroll
                    for (int j = 0; j < 4; j++) {
                        accB[i][j] = fmaf(a[i], bb[j], accB[i][j]);
                        accC[i][j] = fmaf(a[i], cc[j], accC[i][j]);
                    }
            }
        } else {
#pragma unroll
            for (int kk = 0; kk < 16; kk++) {
                float4 a0 = *(const float4*)&As[kk][ty * 8];
                float4 a1 = *(const float4*)&As[kk][ty * 8 + 4];
                float4 bv = *(const float4*)&Bs[kk][tx * 4];
                float a[8] = {a0.x, a0.y, a0.z, a0.w, a1.x, a1.y, a1.z, a1.w};
                float bb[4] = {bv.x, bv.y, bv.z, bv.w};
#pragma unroll
                for (int i = 0; i < 8; i++)
#pragma unroll
                    for (int j = 0; j < 4; j++)
                        accB[i][j] = fmaf(a[i], bb[j], accB[i][j]);
            }
        }
        __syncthreads();
    }

    int ncol = jw0 + tx * 4;
    if (isBC) {
        float4 bB4 = *(const float4*)&b_B[ncol];
        float4 bC4 = *(const float4*)&b_C[ncol];
#pragma unroll
        for (int i = 0; i < 8; i++) {
            int m = m0 + ty * 8 + i;
            float4 o01, o23;
            o01.x = accB[i][0] + bB4.x; o01.y = accC[i][0] + bC4.x;
            o01.z = accB[i][1] + bB4.y; o01.w = accC[i][1] + bC4.y;
            o23.x = accB[i][2] + bB4.z; o23.y = accC[i][2] + bC4.z;
            o23.z = accB[i][3] + bB4.w; o23.w = accC[i][3] + bC4.w;
            *(float4*)&g_BC[m * 192 + ncol]     = o01;
            *(float4*)&g_BC[m * 192 + ncol + 2] = o23;
        }
    } else {
        float bd[4];
#pragma unroll
        for (int j = 0; j < 4; j++) bd[j] = b_dt[ncol + j];
        int c2 = ncol >> 2;
#pragma unroll
        for (int i = 0; i < 8; i++) {
            int m = m0 + ty * 8 + i;
            int b = m >> 12;
            int l = m & 4095;
            int ih = l >> 6;
            int iw = l & 63;
            const float* xb = x + (((b * 48 + c2) * 128 + ih * 2) * 128 + iw * 2);
            float uvals[4];
            uvals[0] = xb[0];
            uvals[1] = xb[1];
            uvals[2] = xb[128];
            uvals[3] = xb[129];
#pragma unroll
            for (int j = 0; j < 4; j++) {
                int dfeat = ncol + j;
                float lin = accB[i][j] + bd[j];
                float dt  = softplus_f(lin);
                float del = softplus_f(dt + bd[j]);
                float u   = uvals[j];
                int o = (b * 192 + dfeat) * LSEQ + l;
                g_dd[o] = make_float2(del, del * u);
                g_uT[o] = u;
            }
        }
    }
}

// ---------------- K2: selective scan, CH=64 ----------------
// 128 blocks x 288 threads. Block covers 3 d's. warp w: dl=w/3, g=w%3;
// lane owns state pair n = g*64+2*lane for d = dbase+dl.
// Per 64-step chunk: two 32-step register bursts (+butterfly each), ONE cp_wait+barrier,
// epilogue handles 2 steps per thread.
#define CH   64

__global__ void __launch_bounds__(288, 1)
scan_kernel(const float* __restrict__ A_log, const float* __restrict__ Dp,
            float* __restrict__ out) {
    extern __shared__ __align__(16) float S[];
    float*  BCf  = S;                        // [2][CH*384] = 49152
    float*  PS3  = S + 49152;                // [2][2 sub][3 g][96] = 1152
    float2* DDsm = (float2*)(PS3 + 1152);    // [2][3][CH] float2 = 768 f2
    float*  Dpsm = (float*)(DDsm + 384);     // [3]+pad

    int tid  = threadIdx.x;
    int w    = tid >> 5;
    int lane = tid & 31;
    int dl   = w / 3;
    int g    = w - dl * 3;
    int b = blockIdx.x >> 6;
    int dbase = (blockIdx.x & 63) * 3;
    int d = dbase + dl;

    int n0 = g * 64 + 2 * lane;
    float A20 = -expf(A_log[d * 192 + n0])     * LOG2E;
    float A21 = -expf(A_log[d * 192 + n0 + 1]) * LOG2E;
    float h0 = 0.0f, h1 = 0.0f;
    if (tid < 3) Dpsm[tid] = Dp[dbase + tid];
    const float SILU1 = 0.73105857863000489f;

    int edl = tid >> 5;
    int es  = tid & 31;
    const float* usrc = g_uT + (b * 192 + dbase + edl) * LSEQ + es;

    const float* BCsrc = (const float*)(g_BC + b * LSEQ * 192);

    float u_cur0 = 0.0f, u_cur1 = 0.0f;
    // prologue: chunk 0
    {
        for (int t = tid; t < 6144; t += 288)
            cp16(BCf + t * 4, BCsrc + t * 4);
        cp_commit();
        if (tid < 96) { u_cur0 = usrc[0]; u_cur1 = usrc[32]; }
        if (w >= 6) {
            const float2* dsrc = g_dd + (b * 192 + dbase + (w - 6)) * LSEQ;
            DDsm[(w - 6) * CH + lane]      = dsrc[lane];
            DDsm[(w - 6) * CH + 32 + lane] = dsrc[32 + lane];
        }
        cp_wait0();
    }
    __syncthreads();

    const int NCHUNK = LSEQ / CH;
    for (int c = 0; c < NCHUNK; c++) {
        int l0  = c * CH;
        int buf = c & 1;

        float2 ddn0 = make_float2(0.f, 0.f), ddn1 = make_float2(0.f, 0.f);
        float u_nxt0 = 0.0f, u_nxt1 = 0.0f;
        if (c + 1 < NCHUNK) {
            const float* bsrc = BCsrc + (l0 + CH) * 384;
            float* bdst = BCf + (buf ^ 1) * 24576;
            for (int t = tid; t < 6144; t += 288)
                cp16(bdst + t * 4, bsrc + t * 4);
            cp_commit();
            if (tid < 96) { u_nxt0 = usrc[l0 + CH]; u_nxt1 = usrc[l0 + CH + 32]; }
            if (w >= 6) {
                const float2* dsrc = g_dd + (b * 192 + dbase + (w - 6)) * LSEQ + l0 + CH;
                ddn0 = dsrc[lane];
                ddn1 = dsrc[32 + lane];
            }
        }

        // ---- two 32-step register bursts ----
#pragma unroll
        for (int sub = 0; sub < 2; sub++) {
            float acc[32];
            const float4* bcp = (const float4*)(BCf + buf * 24576) + sub * 32 * 96 + g * 32 + lane;
            const float2* DDc = DDsm + buf * 192 + dl * CH + sub * 32;
#pragma unroll
            for (int s = 0; s < 32; s++) {
                float2 dd = DDc[s];
                float4 bc = bcp[s * 96];
                float e0 = ex2f(dd.x * A20);
                float e1 = ex2f(dd.x * A21);
                h0 = fmaf(e0, h0, dd.y * bc.x);
                h1 = fmaf(e1, h1, dd.y * bc.z);
                acc[s] = fmaf(h0, bc.y, h1 * bc.w);
            }
            // butterfly: reduce over lanes + transpose (lane l -> step l)
#pragma unroll
            for (int m = 16; m >= 1; m >>= 1) {
                bool hi = (lane & m) != 0;
#pragma unroll
                for (int j = 0; j < m; j++) {
                    float send = hi ? acc[j] : acc[j + m];
                    float recv = __shfl_xor_sync(0xffffffffu, send, m);
                    float keep = hi ? acc[j + m] : acc[j];
                    acc[j] = keep + recv;
                }
            }
            PS3[buf * 576 + sub * 288 + g * 96 + dl * 32 + lane] = acc[0];
        }

        if (w >= 6 && c + 1 < NCHUNK) {
            DDsm[(buf ^ 1) * 192 + (w - 6) * CH + lane]      = ddn0;
            DDsm[(buf ^ 1) * 192 + (w - 6) * CH + 32 + lane] = ddn1;
        }

        cp_wait0();
        __syncthreads();

        // ---- cross-warp sum + epilogue (tid<96): 2 steps per thread ----
        if (tid < 96) {
#pragma unroll
            for (int sub = 0; sub < 2; sub++) {
                int base = buf * 576 + sub * 288 + tid;
                float sum = PS3[base] + PS3[base + 96] + PS3[base + 192];
                float uu  = sub ? u_cur1 : u_cur0;
                float val = (sum + Dpsm[edl] * uu) * SILU1;

                int dd_ = dbase + edl;
                int l = l0 + sub * 32 + es;
                int flat = dd_ * LSEQ + l;
                int i1   = flat / 12288;
                int rem  = flat - i1 * 12288;
                int i2   = rem / 192;
                int r2   = rem - i2 * 192;
                int i3   = r2 >> 2;
                int i4   = (r2 >> 1) & 1;
                int i5   = r2 & 1;
                out[((b * 48 + i3) * 128 + i1 * 2 + i4) * 128 + i2 * 2 + i5] = val;
            }
        }
        u_cur0 = u_nxt0;
        u_cur1 = u_nxt1;
    }
}

// ---------------- launch ----------------
extern "C" void kernel_launch(void* const* d_in, const int* in_sizes, int n_in,
                              void* d_out, int out_size) {
    (void)in_sizes; (void)n_in; (void)out_size;
    const float* x     = (const float*)d_in[0];
    const float* A_log = (const float*)d_in[1];
    const float* Dp    = (const float*)d_in[2];
    const float* W_B   = (const float*)d_in[3];
    const float* b_B   = (const float*)d_in[4];
    const float* W_C   = (const float*)d_in[5];
    const float* b_C   = (const float*)d_in[6];
    const float* W_dt  = (const float*)d_in[7];
    const float* b_dt  = (const float*)d_in[8];
    float* out = (float*)d_out;

    // smem floats: BC 49152 + PS3 1152 + DD 768 + Dp 4 = 51076 (~204KB)
    int smem = (49152 + 1152 + 768 + 4) * (int)sizeof(float);
    static int attr_set = 0;
    if (!attr_set) {
        cudaFuncSetAttribute(scan_kernel, cudaFuncAttributeMaxDynamicSharedMemorySize, smem);
        attr_set = 1;
    }

    dim3 gp(64, 6);
    proj_kernel<<<gp, 256>>>(x, W_B, b_B, W_C, b_C, W_dt, b_dt);
    scan_kernel<<<128, 288, smem>>>(A_log, Dp, out);
}